// round 14
// baseline (speedup 1.0000x reference)
#include <cuda_runtime.h>
#include <cuda_bf16.h>

// BPMLL loss — single graph node, packed-atomic tail, 1-MUFU element math,
// overlap-tuned leader.
//   Identity: sigmoid(x) = 1/2 + tanh(x/2)/2  =>  exp(sigmoid(x)) =
//   e^{1/2} exp(tanh(x/2)/2); all e^{+-1/2} and the e^{-1} bias cancel in
//   pos*neg*e^{-1}. Per element: 1 FMUL + 1 MUFU.TANH + 4 FMA
//   (poly4(t) ~ exp(t/2), t in (-1,1), err ~4e-5).
//   256 blocks x 256 threads; 128 threads/row (2 rows/block), 4 elems/thread.
//   Row reduce: ballot+popc counts (stored to smem BEFORE the butterflies so
//   the leader's LDS can start early) + two interleaved shfl_xor butterflies.
//   Leader: both row denominators' rcp.approx issued back-to-back (MUFU
//   latencies overlap), then ONE atom.add.u64 packing
//   {count: bits>=52, fixed-point sum(2^44): bits<52}; the block seeing
//   count==NBLK-1 holds the grand total in old+add, writes out[0], resets
//   g_pack for graph replay. Fixed-point accumulation is bit-deterministic.

#define ROWS 512
#define COLS 512
#define NBLK 256
#define TPB  256

// exp(t/2) on t in [-1,1], Chebyshev-economized degree 4 (t-basis)
#define P0 1.0f
#define P1 0.49991862f
#define P2 0.125f
#define P3 0.021158854f
#define P4 0.0026041667f

#define INV_ROWS (1.0f / 512.0f)

#define CNT_ONE   (1ULL << 52)
#define SUM_MASK  ((1ULL << 52) - 1ULL)
#define FIX_SCALE 0x1p44f
#define FIX_INV   0x1p-44f

__device__ unsigned long long g_pack = 0ULL;

__device__ __forceinline__ void elem(float c, int y, float& pos, float& neg) {
    float x = __int_as_float(__float_as_int(c) ^ (y << 31)) * 0.5f;
    float t;
    asm("tanh.approx.f32 %0, %1;" : "=f"(t) : "f"(x));   // 1 MUFU
    float h = fmaf(t, P4, P3);
    h = fmaf(h, t, P2);
    h = fmaf(h, t, P1);
    h = fmaf(h, t, P0);
    if (y) pos += h; else neg += h;
}

__global__ __launch_bounds__(TPB) void bpmll_kernel(const float* __restrict__ c,
                                                    const int*   __restrict__ y,
                                                    float* __restrict__ out) {
    const int tid    = threadIdx.x;
    const int lane   = tid & 31;
    const int warp   = tid >> 5;          // 0..7
    const int tid128 = tid & 127;
    const int row    = blockIdx.x * 2 + (tid >> 7);

    const float4 cv = reinterpret_cast<const float4*>(c)[(size_t)row * (COLS / 4) + tid128];
    const int4   yv = reinterpret_cast<const int4*>(y)[(size_t)row * (COLS / 4) + tid128];

    float pos = 0.0f, neg = 0.0f;
    elem(cv.x, yv.x, pos, neg);
    elem(cv.y, yv.y, pos, neg);
    elem(cv.z, yv.z, pos, neg);
    elem(cv.w, yv.w, pos, neg);

    __shared__ float sp[8];
    __shared__ float sn[8];
    __shared__ int   si[8];

    // Counts first (independent of the float math) — store to smem early.
    int ys = __popc(__ballot_sync(0xFFFFFFFFu, yv.x))
           + __popc(__ballot_sync(0xFFFFFFFFu, yv.y))
           + __popc(__ballot_sync(0xFFFFFFFFu, yv.z))
           + __popc(__ballot_sync(0xFFFFFFFFu, yv.w));
    if (lane == 0) si[warp] = ys;

    // Two interleaved butterfly chains — latency overlaps.
    #pragma unroll
    for (int o = 16; o > 0; o >>= 1) {
        pos += __shfl_xor_sync(0xFFFFFFFFu, pos, o);
        neg += __shfl_xor_sync(0xFFFFFFFFu, neg, o);
    }
    if (lane == 0) { sp[warp] = pos; sn[warp] = neg; }
    __syncthreads();

    if (tid == 0) {
        // Row 0 = warps 0-3, row 1 = warps 4-7.
        int   Y0  = (si[0] + si[1]) + (si[2] + si[3]);
        int   Y1  = (si[4] + si[5]) + (si[6] + si[7]);
        float D0f = (float)Y0 * (float)(COLS - Y0);
        float D1f = (float)Y1 * (float)(COLS - Y1);
        // Issue both reciprocals back-to-back: MUFU latencies overlap.
        float R0, R1;
        asm("rcp.approx.f32 %0, %1;" : "=f"(R0) : "f"(D0f));
        asm("rcp.approx.f32 %0, %1;" : "=f"(R1) : "f"(D1f));

        float P0s = (sp[0] + sp[1]) + (sp[2] + sp[3]);
        float N0s = (sn[0] + sn[1]) + (sn[2] + sn[3]);
        float P1s = (sp[4] + sp[5]) + (sp[6] + sp[7]);
        float N1s = (sn[4] + sn[5]) + (sn[6] + sn[7]);

        float part = fmaf(P0s * N0s * INV_ROWS, R0,
                          P1s * N1s * INV_ROWS * R1);

        unsigned long long add = CNT_ONE + __float2ull_rn(part * FIX_SCALE);
        unsigned long long old;
        asm volatile("atom.global.add.u64 %0, [%1], %2;"
                     : "=l"(old) : "l"(&g_pack), "l"(add) : "memory");

        if ((old >> 52) == (unsigned long long)(NBLK - 1)) {
            unsigned long long total_fix = (old + add) & SUM_MASK;
            out[0] = (float)((double)total_fix) * FIX_INV;
            asm volatile("st.global.cg.u64 [%0], %1;"
                         :: "l"(&g_pack), "l"(0ULL) : "memory");
        }
    }
}

extern "C" void kernel_launch(void* const* d_in, const int* in_sizes, int n_in,
                              void* d_out, int out_size) {
    const float* c = (const float*)d_in[0];
    const int*   y = (const int*)d_in[1];
    float*       out = (float*)d_out;
    bpmll_kernel<<<NBLK, TPB>>>(c, y, out);
}